// round 13
// baseline (speedup 1.0000x reference)
#include <cuda_runtime.h>

// HashTables: rolling xor-hash over prefix windows {1,2,4,...,128}, then gather
// 8 embedding rows (64 f32 each) per (b,t) into out[b][t][8*64].
//
// Proven-exact math (R2+): BUCKETS = 2^19 so h % BUCKETS == h & 0x7FFFF and
// only the low 32 bits of token*prime matter -> pure u32 arithmetic. Zero
// tokens XOR as no-ops, so the t-1-j < 0 boundary is a zero-padded smem halo.
//
// R12 -> R13: revert the load batching (+0.288us regression). Frozen at the
// best-measured R10 shape (18.912us; three designs tie there = HBM
// mixed-stream roofline for 126MB irreducible traffic). Single A/B variable:
// output stores .cs -> .wt (write-through). Output is never re-read; .wt
// skips L2 write-allocate, leaving L2 fill bandwidth entirely to the random
// gather stream.

#define T_LEN   4096
#define B_ROWS  8
#define P_TILE  32          // t-positions per block
#define NTHR    256
#define HALO    128
#define MASK19  0x7FFFFu

static __device__ __forceinline__ void stg_wt_f4(float4* p, float4 v) {
    asm volatile("st.global.wt.v4.f32 [%0], {%1, %2, %3, %4};"
                 :: "l"(p), "f"(v.x), "f"(v.y), "f"(v.z), "f"(v.w) : "memory");
}

__global__ __launch_bounds__(NTHR)
void hash_gather_kernel(const int* __restrict__ tokens,         // [B][T] int32
                        const float* __restrict__ tables,       // [8][2^19][64] f32
                        float* __restrict__ out)                // [B][T][512] f32
{
    __shared__ unsigned s_tok[P_TILE + HALO];   // 160 u32
    __shared__ unsigned s_part[P_TILE * 8 * 5]; // c_{1,2,4,8,16} per (pos,lane)
    __shared__ unsigned s_idx[P_TILE * 8];      // bucket ids per (pos, window)

    const unsigned PR[8] = {2654435761u, 2246822519u, 3266489917u, 2028178513u,
                            1220703125u, 1610612741u, 805306457u, 402653189u};

    const int tid = threadIdx.x;
    const int b  = blockIdx.y;
    const int t0 = blockIdx.x * P_TILE;

    // ---- Phase 0: stage tokens, zero-pad before row start ----
    if (tid < P_TILE + HALO) {
        int g = t0 - HALO + tid;
        s_tok[tid] = (g >= 0) ? (unsigned)tokens[(size_t)b * T_LEN + g] : 0u;
    }
    __syncthreads();

    // ---- Phase 1a: per-(pos,lane) partial hash, 16-step chain ----
    {
        const int p = tid >> 3;         // position 0..31
        const int l = tid & 7;          // lane (= j mod 8)
        const unsigned prime = PR[l];
        unsigned* dst = &s_part[(size_t)tid * 5];
        unsigned h = 0;
        int w = 0;
        #pragma unroll
        for (int m = 0; m < 16; m++) {
            // j = l + 8m; token local index p + 127 - j
            h ^= s_tok[p + (HALO - 1) - (l + 8 * m)] * prime;
            const int cnt = m + 1;
            if ((cnt & (cnt - 1)) == 0) {   // cnt in {1,2,4,8,16}
                dst[w] = h;
                w++;
            }
        }
    }
    __syncthreads();

    // ---- Phase 1b: reduce 8 lanes per (pos, window) ----
    {
        const int p = tid >> 3;         // position
        const int w = tid & 7;          // window index, W = 2^w
        const unsigned* base = &s_part[(size_t)p * 40];
        unsigned h = 0;
        if (w >= 3) {
            const int k = w - 3;        // use c_{2^k}
            #pragma unroll
            for (int l = 0; l < 8; l++) h ^= base[l * 5 + k];
        } else {
            const int W = 1 << w;       // 1, 2, or 4 lanes, first term each
            for (int l = 0; l < W; l++) h ^= base[l * 5 + 0];
        }
        s_idx[tid] = h & MASK19;        // s_idx[p*8 + w]
    }
    __syncthreads();

    // ---- Phase 2: table-phased gather + write ----
    const size_t out_base_f4 = ((size_t)b * T_LEN + t0) << 7;   // *128 f4/pos
    const float4* __restrict__ tab4 = (const float4*)tables;
    float4* __restrict__ out4 = (float4*)out;

    const int rowg = tid >> 4;          // 0..15: row slot within iteration
    const int f4   = tid & 15;          // float4 within 64-float row

    #pragma unroll
    for (int k = 0; k < 16; k++) {
        const int tbl = k >> 1;                     // one table per 2 iters
        const int p   = ((k & 1) << 4) + rowg;      // position 0..31
        const unsigned idx = s_idx[p * 8 + tbl];
        const float4 v = __ldg(tab4 + ((((size_t)tbl << 19) + idx) << 4) + f4);
        stg_wt_f4(out4 + out_base_f4 + (((size_t)((p << 3) + tbl)) << 4) + f4, v);
    }
}

extern "C" void kernel_launch(void* const* d_in, const int* in_sizes, int n_in,
                              void* d_out, int out_size) {
    const int* tokens   = (const int*)d_in[0];
    const float* tables = (const float*)d_in[1];
    float* out          = (float*)d_out;

    dim3 grid(T_LEN / P_TILE, B_ROWS);   // (128, 8) = 1024 blocks
    hash_gather_kernel<<<grid, NTHR>>>(tokens, tables, out);
}

// round 15
// speedup vs baseline: 1.2020x; 1.2020x over previous
#include <cuda_runtime.h>

// HashTables: rolling xor-hash over prefix windows {1,2,4,...,128}, then gather
// 8 embedding rows (64 f32 each) per (b,t) into out[b][t][8*64].
//
// Proven-exact math (R2+): BUCKETS = 2^19 so h % BUCKETS == h & 0x7FFFF and
// only the low 32 bits of token*prime matter -> pure u32 arithmetic. Zero
// tokens XOR as no-ops, so the t-1-j < 0 boundary is a zero-padded smem halo.
//
// FINAL (R14 = exact R10 form, 18.912us measured). Session evidence: three
// independent designs tie at 18.912us = ~102% of the realistic mixed-stream
// HBM bound for 126MB irreducible traffic (62MB unique random 256B reads +
// 64MB streaming writes). Falsified levers: deeper MLP (regs + LDGSTS),
// occupancy beyond ~70%, TLB phasing, hash critical path, L2::256B read
// hints (-0.3us), load batching (-0.3us), .wt stores (-4us). Keep: parallel
// 8-lane hash, table-phased gather, plain __ldg loads, .cs evict-first
// stores.

#define T_LEN   4096
#define B_ROWS  8
#define P_TILE  32          // t-positions per block
#define NTHR    256
#define HALO    128
#define MASK19  0x7FFFFu

static __device__ __forceinline__ void stg_cs_f4(float4* p, float4 v) {
    asm volatile("st.global.cs.v4.f32 [%0], {%1, %2, %3, %4};"
                 :: "l"(p), "f"(v.x), "f"(v.y), "f"(v.z), "f"(v.w) : "memory");
}

__global__ __launch_bounds__(NTHR)
void hash_gather_kernel(const int* __restrict__ tokens,         // [B][T] int32
                        const float* __restrict__ tables,       // [8][2^19][64] f32
                        float* __restrict__ out)                // [B][T][512] f32
{
    __shared__ unsigned s_tok[P_TILE + HALO];   // 160 u32
    __shared__ unsigned s_part[P_TILE * 8 * 5]; // c_{1,2,4,8,16} per (pos,lane)
    __shared__ unsigned s_idx[P_TILE * 8];      // bucket ids per (pos, window)

    const unsigned PR[8] = {2654435761u, 2246822519u, 3266489917u, 2028178513u,
                            1220703125u, 1610612741u, 805306457u, 402653189u};

    const int tid = threadIdx.x;
    const int b  = blockIdx.y;
    const int t0 = blockIdx.x * P_TILE;

    // ---- Phase 0: stage tokens, zero-pad before row start ----
    if (tid < P_TILE + HALO) {
        int g = t0 - HALO + tid;
        s_tok[tid] = (g >= 0) ? (unsigned)tokens[(size_t)b * T_LEN + g] : 0u;
    }
    __syncthreads();

    // ---- Phase 1a: per-(pos,lane) partial hash, 16-step chain ----
    {
        const int p = tid >> 3;         // position 0..31
        const int l = tid & 7;          // lane (= j mod 8)
        const unsigned prime = PR[l];
        unsigned* dst = &s_part[(size_t)tid * 5];
        unsigned h = 0;
        int w = 0;
        #pragma unroll
        for (int m = 0; m < 16; m++) {
            // j = l + 8m; token local index p + 127 - j
            h ^= s_tok[p + (HALO - 1) - (l + 8 * m)] * prime;
            const int cnt = m + 1;
            if ((cnt & (cnt - 1)) == 0) {   // cnt in {1,2,4,8,16}
                dst[w] = h;
                w++;
            }
        }
    }
    __syncthreads();

    // ---- Phase 1b: reduce 8 lanes per (pos, window) ----
    {
        const int p = tid >> 3;         // position
        const int w = tid & 7;          // window index, W = 2^w
        const unsigned* base = &s_part[(size_t)p * 40];
        unsigned h = 0;
        if (w >= 3) {
            const int k = w - 3;        // use c_{2^k}
            #pragma unroll
            for (int l = 0; l < 8; l++) h ^= base[l * 5 + k];
        } else {
            const int W = 1 << w;       // 1, 2, or 4 lanes, first term each
            for (int l = 0; l < W; l++) h ^= base[l * 5 + 0];
        }
        s_idx[tid] = h & MASK19;        // s_idx[p*8 + w]
    }
    __syncthreads();

    // ---- Phase 2: table-phased gather + write ----
    const size_t out_base_f4 = ((size_t)b * T_LEN + t0) << 7;   // *128 f4/pos
    const float4* __restrict__ tab4 = (const float4*)tables;
    float4* __restrict__ out4 = (float4*)out;

    const int rowg = tid >> 4;          // 0..15: row slot within iteration
    const int f4   = tid & 15;          // float4 within 64-float row

    #pragma unroll
    for (int k = 0; k < 16; k++) {
        const int tbl = k >> 1;                     // one table per 2 iters
        const int p   = ((k & 1) << 4) + rowg;      // position 0..31
        const unsigned idx = s_idx[p * 8 + tbl];
        const float4 v = __ldg(tab4 + ((((size_t)tbl << 19) + idx) << 4) + f4);
        stg_cs_f4(out4 + out_base_f4 + (((size_t)((p << 3) + tbl)) << 4) + f4, v);
    }
}

extern "C" void kernel_launch(void* const* d_in, const int* in_sizes, int n_in,
                              void* d_out, int out_size) {
    const int* tokens   = (const int*)d_in[0];
    const float* tables = (const float*)d_in[1];
    float* out          = (float*)d_out;

    dim3 grid(T_LEN / P_TILE, B_ROWS);   // (128, 8) = 1024 blocks
    hash_gather_kernel<<<grid, NTHR>>>(tokens, tables, out);
}